// round 17
// baseline (speedup 1.0000x reference)
#include <cuda_runtime.h>
#include <cuda_fp16.h>
#include <cstdint>

// ---------------- problem constants ----------------
#define N_NODES 26240      // B * N_PER = 128 * 205 (exactly 205 blocks of 128)
#define HDIM    200
#define NEDGE   209920
#define BATCH   128
#define NPER    205
#define EMBD    768
#define SEQ     512
#define NLAYERS 6
#define KPAD    208        // padded K (fp16 single pass; 3x64 + 1x16 tiles)

// ---------------- static device scratch ----------------
__device__ float g_h0[N_NODES * HDIM];
__device__ float g_h1[N_NODES * HDIM];
__device__ float g_gi[N_NODES * 3 * HDIM];
__device__ float g_gh[N_NODES * 3 * HDIM];
__device__ float g_feats[BATCH * 800];
__device__ int   g_deg[N_NODES];
__device__ int   g_rs [N_NODES + 1];
__device__ int   g_cur[N_NODES];
__device__ int   g_csrc[NEDGE];

// GGC fp16 operands, K-padded to 208 (pads zero from module init, never written)
__device__ __align__(16) __half g_h16[(size_t)N_NODES * KPAD];
__device__ __align__(16) __half g_a16[(size_t)N_NODES * KPAD];
// GGC fp16 weights
__device__ __align__(16) __half g_wi16[640 * KPAD];             // wih, rows 600..639 zero
__device__ __align__(16) __half g_wh16[640 * KPAD];             // whh, rows 600..639 zero
__device__ __align__(16) __half g_wgd16[NLAYERS * 208 * KPAD];  // ggc_w[l] direct cast
__device__ __align__(16) __half g_wc16[NLAYERS * 640 * KPAD];   // Wcomb_l = wih @ W_l^T

// fp16 embeddings, time-major [b][t][c], +8 zero rows for tap overrun
__device__ __align__(16) __half g_e16[((size_t)BATCH * SEQ + 8) * EMBD];
// fp16 conv weights: [200][K], tap-major K (single pass)
__device__ __align__(16) __half g_w1h[200 * 2304];
__device__ __align__(16) __half g_w2h[200 * 3072];
__device__ __align__(16) __half g_w3h[200 * 3840];
// conv0: fp16 padded h input [BATCH][260][256] and weights [208][768]
__device__ __align__(16) __half g_hp16[(size_t)BATCH * 260 * 256];
__device__ __align__(16) __half g_w0h[208 * 768];

// ---------------- warp-level MMA (compute_100-safe PTX) ----------------
#define MMA_F16(d, a, b0, b1) asm volatile(                            \
    "mma.sync.aligned.m16n8k16.row.col.f32.f16.f16.f32 "               \
    "{%0,%1,%2,%3}, {%4,%5,%6,%7}, {%8,%9}, {%0,%1,%2,%3};"            \
    : "+f"((d)[0]), "+f"((d)[1]), "+f"((d)[2]), "+f"((d)[3])           \
    : "r"((a)[0]), "r"((a)[1]), "r"((a)[2]), "r"((a)[3]),              \
      "r"(b0), "r"(b1))

// ---------------- cp.async helpers (sm_80+ PTX) ----------------
#define CP16(dst, src) asm volatile("cp.async.ca.shared.global [%0], [%1], 16;" \
                                    :: "r"(dst), "l"(src))
#define CP_COMMIT() asm volatile("cp.async.commit_group;" ::: "memory")
#define CP_WAIT0()  asm volatile("cp.async.wait_group 0;" ::: "memory")

__device__ __forceinline__ uint32_t s2u(const void* p) {
    return (uint32_t)__cvta_generic_to_shared(p);
}

// ---------------- shared copy helper for K=208 (3x64 + 1x16) -----------------
__device__ __forceinline__ void cp_k208(const __half* A, const __half* B,
                                        uint32_t ab, uint32_t bb,
                                        int tid, int kt) {
    const int kg = kt * 64;
    constexpr int ASTR = 72, BSTR = 72;
    if (kt < 3) {
#pragma unroll
        for (int i = 0; i < 4; i++) {
            int u = tid + i * 256;
            int row = u >> 3, ch = u & 7;
            CP16(ab + (row * ASTR + ch * 8) * 2,
                 A + (long long)row * KPAD + kg + ch * 8);
        }
#pragma unroll
        for (int i = 0; i < 7; i++) {
            int u = tid + i * 256;
            if (u < 1664) {
                int row = u >> 3, ch = u & 7;
                CP16(bb + (row * BSTR + ch * 8) * 2,
                     B + (long long)row * KPAD + kg + ch * 8);
            }
        }
    } else {   // 16-wide tail, cols 192..207
        {
            int row = tid >> 1, ch = tid & 1;
            CP16(ab + (row * ASTR + ch * 8) * 2,
                 A + (long long)row * KPAD + kg + ch * 8);
        }
#pragma unroll
        for (int i = 0; i < 2; i++) {
            int u = tid + i * 256;
            if (u < 416) {
                int row = u >> 1, ch = u & 1;
                CP16(bb + (row * BSTR + ch * 8) * 2,
                     B + (long long)row * KPAD + kg + ch * 8);
            }
        }
    }
}

// ---------------- GGC GEMM: C = A @ Bfull^T slice (fp16, K=208) ----------------
// grid (3 n-tiles, 205 m-tiles). Bfull is [640][208]; slice nb covers cols nb*208.
__global__ void __launch_bounds__(256, 1) ggcN_k(
    const __half* __restrict__ Ag,
    const __half* __restrict__ Bfull,
    float* __restrict__ C)
{
    extern __shared__ __align__(16) char dsm[];
    constexpr int ASTR = 72, BSTR = 72;
    __half* As = (__half*)dsm;
    __half* Bs = (__half*)(dsm + 36864);

    const int tid = threadIdx.x;
    const int lane = tid & 31, wid = tid >> 5;
    const int wm = wid & 3, wn = wid >> 2;
    const int g = lane >> 2, t2 = (lane & 3) * 2;
    const int m0 = blockIdx.y * 128;
    const int nb = blockIdx.x;
    const uint32_t asb = s2u(As), bsb = s2u(Bs);

    const __half* A = Ag + (long long)m0 * KPAD;
    const __half* B = Bfull + (long long)nb * 208 * KPAD;
    const int cb = nb * 208;

    float acc[2][13][4];
#pragma unroll
    for (int i = 0; i < 2; i++)
#pragma unroll
        for (int j = 0; j < 13; j++)
#pragma unroll
            for (int q = 0; q < 4; q++) acc[i][j][q] = 0.f;

    cp_k208(A, B, asb, bsb, tid, 0); CP_COMMIT(); CP_WAIT0();
    __syncthreads();

#pragma unroll 1
    for (int kt = 0; kt < 4; kt++) {
        const int buf = kt & 1;
        const bool more = (kt + 1 < 4);
        if (more) {
            cp_k208(A, B, asb + (buf ^ 1) * 128 * ASTR * 2,
                    bsb + (buf ^ 1) * 208 * BSTR * 2, tid, kt + 1);
            CP_COMMIT();
        }
        const __half* Ab = As + buf * 128 * ASTR;
        const __half* Bb = Bs + buf * 208 * BSTR;
        const int ksteps = (kt == 3) ? 1 : 4;
#pragma unroll 1
        for (int ks = 0; ks < ksteps; ks++) {
            const int ko = ks * 16;
            uint32_t a[2][4];
#pragma unroll
            for (int i = 0; i < 2; i++) {
                const int r = wm * 32 + i * 16 + g;
                a[i][0] = *(const uint32_t*)(Ab + (r)     * ASTR + ko + t2);
                a[i][1] = *(const uint32_t*)(Ab + (r + 8) * ASTR + ko + t2);
                a[i][2] = *(const uint32_t*)(Ab + (r)     * ASTR + ko + t2 + 8);
                a[i][3] = *(const uint32_t*)(Ab + (r + 8) * ASTR + ko + t2 + 8);
            }
            uint32_t bf[13][2];
#pragma unroll
            for (int j = 0; j < 13; j++) {
                const int n = wn * 104 + j * 8 + g;
                bf[j][0] = *(const uint32_t*)(Bb + n * BSTR + ko + t2);
                bf[j][1] = *(const uint32_t*)(Bb + n * BSTR + ko + t2 + 8);
            }
#pragma unroll
            for (int j = 0; j < 13; j++) {
                MMA_F16(acc[0][j], a[0], bf[j][0], bf[j][1]);
                MMA_F16(acc[1][j], a[1], bf[j][0], bf[j][1]);
            }
        }
        if (more) CP_WAIT0();
        __syncthreads();
    }

#pragma unroll
    for (int i = 0; i < 2; i++) {
        const int r = m0 + wm * 32 + i * 16 + g;
#pragma unroll
        for (int j = 0; j < 13; j++) {
            const int col = cb + wn * 104 + j * 8 + t2;
            if (col < 600) {
                C[(long long)r * 600 + col]       = acc[i][j][0];
                C[(long long)(r + 8) * 600 + col] = acc[i][j][2];
            }
            if (col + 1 < 600) {
                C[(long long)r * 600 + col + 1]       = acc[i][j][1];
                C[(long long)(r + 8) * 600 + col + 1] = acc[i][j][3];
            }
        }
    }
}

// ---------------- Wcomb = wih @ W_l^T (fp16 out) ----------------
// grid (1, 5 m-tiles, 6 layers). C[l][j:640][k1:208] fp16.
__global__ void __launch_bounds__(256, 1) wcomb_k(
    const __half* __restrict__ wi,      // [640][208]
    const __half* __restrict__ wgd,     // [L][208][208]
    __half* __restrict__ wc)            // [L][640][208]
{
    extern __shared__ __align__(16) char dsm[];
    constexpr int ASTR = 72, BSTR = 72;
    __half* As = (__half*)dsm;
    __half* Bs = (__half*)(dsm + 36864);

    const int tid = threadIdx.x;
    const int lane = tid & 31, wid = tid >> 5;
    const int wm = wid & 3, wn = wid >> 2;
    const int g = lane >> 2, t2 = (lane & 3) * 2;
    const int m0 = blockIdx.y * 128;
    const int l = blockIdx.z;
    const uint32_t asb = s2u(As), bsb = s2u(Bs);

    const __half* A = wi + (long long)m0 * KPAD;
    const __half* B = wgd + (long long)l * 208 * KPAD;
    __half* C = wc + (long long)l * 640 * KPAD;

    float acc[2][13][4];
#pragma unroll
    for (int i = 0; i < 2; i++)
#pragma unroll
        for (int j = 0; j < 13; j++)
#pragma unroll
            for (int q = 0; q < 4; q++) acc[i][j][q] = 0.f;

    cp_k208(A, B, asb, bsb, tid, 0); CP_COMMIT(); CP_WAIT0();
    __syncthreads();

#pragma unroll 1
    for (int kt = 0; kt < 4; kt++) {
        const int buf = kt & 1;
        const bool more = (kt + 1 < 4);
        if (more) {
            cp_k208(A, B, asb + (buf ^ 1) * 128 * ASTR * 2,
                    bsb + (buf ^ 1) * 208 * BSTR * 2, tid, kt + 1);
            CP_COMMIT();
        }
        const __half* Ab = As + buf * 128 * ASTR;
        const __half* Bb = Bs + buf * 208 * BSTR;
        const int ksteps = (kt == 3) ? 1 : 4;
#pragma unroll 1
        for (int ks = 0; ks < ksteps; ks++) {
            const int ko = ks * 16;
            uint32_t a[2][4];
#pragma unroll
            for (int i = 0; i < 2; i++) {
                const int r = wm * 32 + i * 16 + g;
                a[i][0] = *(const uint32_t*)(Ab + (r)     * ASTR + ko + t2);
                a[i][1] = *(const uint32_t*)(Ab + (r + 8) * ASTR + ko + t2);
                a[i][2] = *(const uint32_t*)(Ab + (r)     * ASTR + ko + t2 + 8);
                a[i][3] = *(const uint32_t*)(Ab + (r + 8) * ASTR + ko + t2 + 8);
            }
            uint32_t bf[13][2];
#pragma unroll
            for (int j = 0; j < 13; j++) {
                const int n = wn * 104 + j * 8 + g;
                bf[j][0] = *(const uint32_t*)(Bb + n * BSTR + ko + t2);
                bf[j][1] = *(const uint32_t*)(Bb + n * BSTR + ko + t2 + 8);
            }
#pragma unroll
            for (int j = 0; j < 13; j++) {
                MMA_F16(acc[0][j], a[0], bf[j][0], bf[j][1]);
                MMA_F16(acc[1][j], a[1], bf[j][0], bf[j][1]);
            }
        }
        if (more) CP_WAIT0();
        __syncthreads();
    }

#pragma unroll
    for (int i = 0; i < 2; i++) {
        const int r = m0 + wm * 32 + i * 16 + g;
#pragma unroll
        for (int j = 0; j < 13; j++) {
            const int col = wn * 104 + j * 8 + t2;
            if (col < 208) {
                C[(long long)r * KPAD + col]       = __float2half(acc[i][j][0]);
                C[(long long)(r + 8) * KPAD + col] = __float2half(acc[i][j][2]);
            }
            if (col + 1 < 208) {
                C[(long long)r * KPAD + col + 1]       = __float2half(acc[i][j][1]);
                C[(long long)(r + 8) * KPAD + col + 1] = __float2half(acc[i][j][3]);
            }
        }
    }
}

// ---------------- fused conv1/2/3: fp16 conv-as-GEMM, BN=112, 2 CTAs/SM -------
struct Conv3Args {
    const __half* wb[3];
    const float* bias[3];
};
// grid (6 = 3 convs x 2 n-tiles, 4 m-tiles, 128 batches)
__global__ void __launch_bounds__(256, 2) conv3h_k(
    const __half* __restrict__ e16,
    Conv3Args args,
    float* __restrict__ feats)
{
    extern __shared__ __align__(16) char dsm[];
    constexpr int ASTR = 72, BSTR = 72;
    __half* As = (__half*)dsm;                     // [2][128][72] = 36864 B
    __half* Bs = (__half*)(dsm + 36864);           // [2][112][72] = 32256 B
    float* smax  = (float*)(dsm + 36864 + 32256);  // [112]
    float* sbias = smax + 112;                     // [112]

    const int cid = blockIdx.x >> 1;
    const int nb  = blockIdx.x & 1;
    const int n0  = nb * 112;
    const int M   = (cid == 0) ? 510 : (cid == 1) ? 509 : 508;
    const int K   = (cid == 0) ? 2304 : (cid == 1) ? 3072 : 3840;
    const int featOff = 200 + cid * 200;
    const __half* wb = args.wb[cid];
    const float* bias = args.bias[cid];

    const int tid = threadIdx.x;
    const int lane = tid & 31, wid = tid >> 5;
    const int wm = wid & 3, wn = wid >> 2;
    const int g = lane >> 2, t2 = (lane & 3) * 2;
    const int b = blockIdx.z, m0 = blockIdx.y * 128;
    const int T = K / 64;
    const uint32_t asb = s2u(As), bsb = s2u(Bs);

    if (tid < 112) {
        smax[tid] = 0.f;
        sbias[tid] = (n0 + tid < 200) ? bias[n0 + tid] : 0.f;
    }

    auto copy_tile = [&](int kt, int buf) {
        int kk = kt / 12;
        int c0 = (kt - kk * 12) * 64;
        long long abase = ((long long)(b * SEQ + m0 + kk)) * EMBD + c0;
        const uint32_t ab = asb + buf * 128 * ASTR * 2;
        const uint32_t bb = bsb + buf * 112 * BSTR * 2;
#pragma unroll
        for (int i = 0; i < 4; i++) {
            int u = tid + i * 256;                 // 1024 x 16B
            int row = u >> 3, ch = u & 7;
            CP16(ab + (row * ASTR + ch * 8) * 2,
                 e16 + abase + (long long)row * EMBD + ch * 8);
        }
        int kg = kt * 64;
#pragma unroll
        for (int i = 0; i < 4; i++) {
            int u = tid + i * 256;                 // 896 x 16B (112 rows)
            if (u < 896) {
                int row = u >> 3, ch = u & 7;
                int grow = n0 + row;
                if (grow > 199) grow = 199;        // clamp: stay in-bounds
                CP16(bb + (row * BSTR + ch * 8) * 2,
                     wb + (long long)grow * K + kg + ch * 8);
            }
        }
    };

    float acc[2][7][4];
#pragma unroll
    for (int i = 0; i < 2; i++)
#pragma unroll
        for (int j = 0; j < 7; j++)
#pragma unroll
            for (int q = 0; q < 4; q++) acc[i][j][q] = 0.f;

    copy_tile(0, 0); CP_COMMIT(); CP_WAIT0();
    __syncthreads();

#pragma unroll 1
    for (int kt = 0; kt < T; kt++) {
        const int buf = kt & 1;
        const bool more = (kt + 1 < T);
        if (more) { copy_tile(kt + 1, buf ^ 1); CP_COMMIT(); }

        const __half* Ab = As + buf * 128 * ASTR;
        const __half* Bb = Bs + buf * 112 * BSTR;
#pragma unroll
        for (int ks = 0; ks < 4; ks++) {
            const int ko = ks * 16;
            uint32_t a[2][4];
#pragma unroll
            for (int i = 0; i < 2; i++) {
                const int r = wm * 32 + i * 16 + g;
                a[i][0] = *(const uint32_t*)(Ab + (r)     * ASTR + ko + t2);
                a[i][1] = *(const uint32_t*)(Ab + (r + 8) * ASTR + ko + t2);
                a[i][2] = *(const uint32_t*)(Ab + (r)     * ASTR + ko + t2 + 8);
                a[i][3] = *(const uint32_t*)(Ab + (r + 8) * ASTR + ko + t2 + 8);
            }
            uint32_t bf[7][2];
#pragma unroll
            for (int j = 0; j < 7; j++) {
                const int n = wn * 56 + j * 8 + g;
                bf[j][0] = *(const uint32_t*)(Bb + n * BSTR + ko + t2);
                bf[j][1] = *(const uint32_t*)(Bb + n * BSTR + ko + t2 + 8);
            }
#pragma unroll
            for (int j = 0; j < 7; j++) {
                MMA_F16(acc[0][j], a[0], bf[j][0], bf[j][1]);
                MMA_F16(acc[1][j], a[1], bf[j][0], bf[j][1]);
            }
        }
        if (more) CP_WAIT0();
        __syncthreads();
    }

    const int valid = (M - m0 < 128) ? (M - m0) : 128;
#pragma unroll
    for (int j = 0; j < 7; j++) {
        float v0 = -1e30f, v1 = -1e30f;
#pragma unroll
        for (int i = 0; i < 2; i++) {
            const int r0 = wm * 32 + i * 16 + g;
            if (r0 < valid)     { v0 = fmaxf(v0, acc[i][j][0]); v1 = fmaxf(v1, acc[i][j][1]); }
            if (r0 + 8 < valid) { v0 = fmaxf(v0, acc[i][j][2]); v1 = fmaxf(v1, acc[i][j][3]); }
        }
#pragma unroll
        for (int o = 4; o <= 16; o <<= 1) {
            v0 = fmaxf(v0, __shfl_xor_sync(~0u, v0, o));
            v1 = fmaxf(v1, __shfl_xor_sync(~0u, v1, o));
        }
        if (g == 0) {
            const int lc = wn * 56 + j * 8 + t2;   // local col within tile
            if (n0 + lc < 200) {
                float r = fmaxf(v0 + sbias[lc], 0.f);
                atomicMax((unsigned int*)&smax[lc], __float_as_uint(r));
            }
            if (n0 + lc + 1 < 200) {
                float r = fmaxf(v1 + sbias[lc + 1], 0.f);
                atomicMax((unsigned int*)&smax[lc + 1], __float_as_uint(r));
            }
        }
    }
    __syncthreads();
    if (tid < 112 && n0 + tid < 200)
        atomicMax((unsigned int*)&feats[(long long)b * 800 + featOff + n0 + tid],
                  __float_as_uint(smax[tid]));
}

// ---------------- conv0: fp16 conv-as-GEMM over padded h ----------------
// grid (1, 2 m-tiles, 128 batches). M = 205, N = 200, feats cols 0..199.
__global__ void __launch_bounds__(256, 1) conv0h_k(
    const __half* __restrict__ hp16,
    const __half* __restrict__ w0h,     // [208][768] (rows 200..207 zero)
    const float* __restrict__ bias,
    float* __restrict__ feats)
{
    extern __shared__ __align__(16) char dsm[];
    constexpr int ASTR = 72, BSTR = 72;
    __half* As = (__half*)dsm;
    __half* Bs = (__half*)(dsm + 36864);
    float* smax  = (float*)(dsm + 36864 + 59904);
    float* sbias = smax + 208;

    const int tid = threadIdx.x;
    const int lane = tid & 31, wid = tid >> 5;
    const int wm = wid & 3, wn = wid >> 2;
    const int g = lane >> 2, t2 = (lane & 3) * 2;
    const int b = blockIdx.z, m0 = blockIdx.y * 128;
    const uint32_t asb = s2u(As), bsb = s2u(Bs);

    if (tid < 208) { smax[tid] = 0.f; sbias[tid] = (tid < 200) ? bias[tid] : 0.f; }

    auto copy_tile = [&](int kt, int buf) {
        int kk = kt >> 2;
        int c0 = (kt & 3) * 64;
        long long abase = ((long long)b * 260 + m0 + kk) * 256 + c0;
        const uint32_t ab = asb + buf * 128 * ASTR * 2;
        const uint32_t bb = bsb + buf * 208 * BSTR * 2;
#pragma unroll
        for (int i = 0; i < 4; i++) {
            int u = tid + i * 256;
            int row = u >> 3, ch = u & 7;
            CP16(ab + (row * ASTR + ch * 8) * 2,
                 hp16 + abase + (long long)row * 256 + ch * 8);
        }
        int kg = kt * 64;
#pragma unroll
        for (int i = 0; i < 7; i++) {
            int u = tid + i * 256;
            if (u < 1664) {
                int row = u >> 3, ch = u & 7;
                CP16(bb + (row * BSTR + ch * 8) * 2,
                     w0h + (long long)row * 768 + kg + ch * 8);
            }
        }
    };

    float acc[2][13][4];
#pragma unroll
    for (int i = 0; i < 2; i++)
#pragma unroll
        for (int j = 0; j < 13; j++)
#pragma unroll
            for (int q = 0; q < 4; q++) acc[i][j][q] = 0.f;

    copy_tile(0, 0); CP_COMMIT(); CP_WAIT0();
    __syncthreads();

#pragma unroll 1
    for (int kt = 0; kt < 12; kt++) {
        const int buf = kt & 1;
        const bool more = (kt + 1 < 12);
        if (more) { copy_tile(kt + 1, buf ^ 1); CP_COMMIT(); }

        const __half* Ab = As + buf * 128 * ASTR;
        const __half* Bb = Bs + buf * 208 * BSTR;
#pragma unroll
        for (int ks = 0; ks < 4; ks++) {
            const int ko = ks * 16;
            uint32_t a[2][4];
#pragma unroll
            for (int i = 0; i < 2; i++) {
                const int r = wm * 32 + i * 16 + g;
                a[i][0] = *(const uint32_t*)(Ab + (r)     * ASTR + ko + t2);
                a[i][1] = *(const uint32_t*)(Ab + (r + 8) * ASTR + ko + t2);
                a[i][2] = *(const uint32_t*)(Ab + (r)     * ASTR + ko + t2 + 8);
                a[i][3] = *(const uint32_t*)(Ab + (r + 8) * ASTR + ko + t2 + 8);
            }
            uint32_t bf[13][2];
#pragma unroll
            for (int j = 0; j < 13; j++) {
                const int n = wn * 104 + j * 8 + g;
                bf[j][0] = *(const uint32_t*)(Bb + n * BSTR + ko + t2);
                bf[j][1] = *(const uint32_t*)(Bb + n * BSTR + ko + t2 + 8);
            }
#pragma unroll
            for (int j = 0; j < 13; j++) {
                MMA_F16(acc[0][j], a[0], bf[j][0], bf[j][1]);
                MMA_F16(acc[1][j], a[1], bf[j][0], bf[j][1]);
            }
        }
        if (more) CP_WAIT0();
        __syncthreads();
    }

    const int valid = (205 - m0 < 128) ? (205 - m0) : 128;
#pragma unroll
    for (int j = 0; j < 13; j++) {
        float v0 = -1e30f, v1 = -1e30f;
#pragma unroll
        for (int i = 0; i < 2; i++) {
            const int r0 = wm * 32 + i * 16 + g;
            if (r0 < valid)     { v0 = fmaxf(v0, acc[i][j][0]); v1 = fmaxf(v1, acc[i][j][1]); }
            if (r0 + 8 < valid) { v0 = fmaxf(v0, acc[i][j][2]); v1 = fmaxf(v1, acc[i][j][3]); }
        }
#pragma unroll
        for (int o = 4; o <= 16; o <<= 1) {
            v0 = fmaxf(v0, __shfl_xor_sync(~0u, v0, o));
            v1 = fmaxf(v1, __shfl_xor_sync(~0u, v1, o));
        }
        if (g == 0) {
            const int col = wn * 104 + j * 8 + t2;
            if (col < 200) {
                float r = fmaxf(v0 + sbias[col], 0.f);
                atomicMax((unsigned int*)&smax[col], __float_as_uint(r));
            }
            if (col + 1 < 200) {
                float r = fmaxf(v1 + sbias[col + 1], 0.f);
                atomicMax((unsigned int*)&smax[col + 1], __float_as_uint(r));
            }
        }
    }
    __syncthreads();
    if (tid < 200)
        atomicMax((unsigned int*)&feats[(long long)b * 800 + tid],
                  __float_as_uint(smax[tid]));
}

// ---------------- fp16 embed ----------------
__global__ void k_embed16(const int* __restrict__ ids, const float* __restrict__ tbl,
                          __half* __restrict__ e16) {
    int row = blockIdx.x;
    int t = threadIdx.x;
    long long o = (long long)row * EMBD;
    if (row >= BATCH * SEQ) {
        if (t < 96) {
            ((uint2*)(e16 + o))[t * 2]     = make_uint2(0, 0);
            ((uint2*)(e16 + o))[t * 2 + 1] = make_uint2(0, 0);
        }
        return;
    }
    long long id = ids[row];
    float4 v = ((const float4*)(tbl + id * EMBD))[t];
    __half2 h01 = __floats2half2_rn(v.x, v.y);
    __half2 h23 = __floats2half2_rn(v.z, v.w);
    uint2 hv;
    hv.x = *(uint32_t*)&h01; hv.y = *(uint32_t*)&h23;
    ((uint2*)(e16 + o))[t] = hv;
}

// w: [200][768][KK] fp32 -> wb: [200][K] fp16, tap-major K
__global__ void k_w16(const float* __restrict__ w, __half* __restrict__ wb, int KK) {
    int K = 768 * KK;
    int idx = blockIdx.x * blockDim.x + threadIdx.x;
    if (idx >= 200 * K) return;
    int co = idx / K, r = idx - co * K;
    int kk = r / 768, ci = r - kk * 768;
    wb[idx] = __float2half(w[(co * 768 + ci) * KK + kk]);
}

// conv0 weights: c0w [200][200][3] -> w0h [208][768] (col = kk*256 + ci)
__global__ void k_w0h(const float* __restrict__ w, __half* __restrict__ out) {
    int idx = blockIdx.x * blockDim.x + threadIdx.x;
    if (idx >= 200 * 600) return;
    int co = idx / 600, r = idx - co * 600;
    int kk = r / 200, ci = r - kk * 200;
    out[(long long)co * 768 + kk * 256 + ci] =
        __float2half(w[(co * 200 + ci) * 3 + kk]);
}

// ggc_w direct cast: [L][208 rows k1][208 cols k2]
__global__ void k_wgd16(const float* __restrict__ w, __half* __restrict__ out) {
    int idx = blockIdx.x * blockDim.x + threadIdx.x;
    if (idx >= NLAYERS * 208 * KPAD) return;
    int l = idx / (208 * KPAD);
    int rem = idx - l * 208 * KPAD;
    int k1 = rem / KPAD, k2 = rem - k1 * KPAD;
    float x = (k1 < 200 && k2 < 200) ? w[(long long)l * 40000 + k1 * 200 + k2] : 0.f;
    out[idx] = __float2half(x);
}

// wih/whh [600][200] -> [640][208], zero pad
__global__ void k_wgru16(const float* __restrict__ w, __half* __restrict__ out) {
    int idx = blockIdx.x * blockDim.x + threadIdx.x;
    if (idx >= 640 * KPAD) return;
    int n = idx / KPAD, kk = idx - n * KPAD;
    float x = (n < 600 && kk < 200) ? w[n * 200 + kk] : 0.f;
    out[idx] = __float2half(x);
}

// x [26240][200] fp32 -> h16 [26240][208] fp16 (pads zeroed here, forever)
__global__ void k_x16(const float* __restrict__ xin, __half* __restrict__ h16) {
    int idx = blockIdx.x * blockDim.x + threadIdx.x;
    if (idx >= N_NODES * KPAD) return;
    int n = idx / KPAD, c = idx - n * KPAD;
    h16[idx] = __float2half((c < 200) ? xin[n * HDIM + c] : 0.f);
}

// ---------------- CSR build ----------------
__global__ void k_hist(const int* __restrict__ ei, int* __restrict__ deg) {
    int i = blockIdx.x * blockDim.x + threadIdx.x;
    if (i < NEDGE) atomicAdd(&deg[ei[NEDGE + i]], 1);
}

__global__ void k_scan(const int* __restrict__ deg, int* __restrict__ rs,
                       int* __restrict__ cur, int n) {
    __shared__ int s[1024];
    __shared__ int carry;
    int t = threadIdx.x;
    if (t == 0) carry = 0;
    __syncthreads();
    for (int base = 0; base < n; base += 1024) {
        int v = (base + t < n) ? deg[base + t] : 0;
        s[t] = v;
        __syncthreads();
        for (int off = 1; off < 1024; off <<= 1) {
            int add = (t >= off) ? s[t - off] : 0;
            __syncthreads();
            s[t] += add;
            __syncthreads();
        }
        int c0 = carry;
        int ex = c0 + s[t] - v;
        if (base + t < n) { rs[base + t] = ex; cur[base + t] = ex; }
        __syncthreads();
        if (t == 0) carry = c0 + s[1023];
        __syncthreads();
    }
    if (t == 0) rs[n] = carry;
}

__global__ void k_fill(const int* __restrict__ ei, int* __restrict__ cur,
                       int* __restrict__ cs) {
    int i = blockIdx.x * blockDim.x + threadIdx.x;
    if (i < NEDGE) {
        int d = ei[NEDGE + i];
        int p = atomicAdd(&cur[d], 1);
        cs[p] = ei[i];
    }
}

// ---------------- segment-sum of h (fp32 source) + fp16 write --------------
__global__ void k_agg(const float* __restrict__ h, const int* __restrict__ rs,
                      const int* __restrict__ cs, __half* __restrict__ a16) {
    int w = (blockIdx.x * blockDim.x + threadIdx.x) >> 5;
    int lane = threadIdx.x & 31;
    if (w >= N_NODES) return;
    int s = rs[w], e = rs[w + 1];
    float a[7] = {0, 0, 0, 0, 0, 0, 0};
    int i = s;
    for (; i + 1 < e; i += 2) {
        const float* r0 = h + (long long)cs[i]     * HDIM;
        const float* r1 = h + (long long)cs[i + 1] * HDIM;
        a[0] += r0[lane]       + r1[lane];
        a[1] += r0[lane +  32] + r1[lane +  32];
        a[2] += r0[lane +  64] + r1[lane +  64];
        a[3] += r0[lane +  96] + r1[lane +  96];
        a[4] += r0[lane + 128] + r1[lane + 128];
        a[5] += r0[lane + 160] + r1[lane + 160];
        if (lane < 8) a[6] += r0[lane + 192] + r1[lane + 192];
    }
    if (i < e) {
        const float* r0 = h + (long long)cs[i] * HDIM;
        a[0] += r0[lane];       a[1] += r0[lane + 32];  a[2] += r0[lane + 64];
        a[3] += r0[lane + 96];  a[4] += r0[lane + 128]; a[5] += r0[lane + 160];
        if (lane < 8) a[6] += r0[lane + 192];
    }
    long long o = (long long)w * KPAD + lane;
#pragma unroll
    for (int q = 0; q < 6; q++) a16[o + q * 32] = __float2half(a[q]);
    if (lane < 8) a16[o + 192] = __float2half(a[6]);
}

// ---------------- GRU gates (+ bias fold + fp16 h; optional hp16 write) ----------
__global__ void k_gates(const float* __restrict__ gi, const float* __restrict__ gh,
                        const float* __restrict__ bih, const float* __restrict__ bhh,
                        const float* __restrict__ hsrc, float* __restrict__ hdst,
                        __half* __restrict__ h16, __half* __restrict__ hp) {
    int idx = blockIdx.x * blockDim.x + threadIdx.x;
    if (idx >= N_NODES * HDIM) return;
    int n = idx / HDIM, c = idx - n * HDIM;
    const float* giN = gi + (long long)n * 600;
    const float* ghN = gh + (long long)n * 600;
    float r  = 1.f / (1.f + expf(-(giN[c] + bih[c] + ghN[c] + bhh[c])));
    float z  = 1.f / (1.f + expf(-(giN[200 + c] + bih[200 + c] + ghN[200 + c] + bhh[200 + c])));
    float nn = tanhf(giN[400 + c] + bih[400 + c] + r * (ghN[400 + c] + bhh[400 + c]));
    float h = (1.f - z) * nn + z * hsrc[idx];
    hdst[idx] = h;
    __half hf = __float2half(h);
    h16[(long long)n * KPAD + c] = hf;
    if (hp) {
        int b = n / NPER, rr = n - b * NPER;
        hp[((long long)b * 260 + rr + 1) * 256 + c] = hf;
    }
}

// ---------------- fused FC head ----------------
__global__ void k_fc(const float* __restrict__ feats,
                     const float* __restrict__ w1, const float* __restrict__ b1,
                     const float* __restrict__ w2, const float* __restrict__ b2,
                     const float* __restrict__ w3, const float* __restrict__ b3,
                     float* __restrict__ out) {
    int b = blockIdx.x;
    int tid = threadIdx.x;
    int lane = tid & 31, wrp = tid >> 5;
    __shared__ float sf[800];
    __shared__ float s1[256];
    __shared__ float s2[128];
    for (int i = tid; i < 800; i += 256) sf[i] = feats[b * 800 + i];
    __syncthreads();
    for (int jj = 0; jj < 32; jj++) {
        int j = wrp * 32 + jj;
        float a = 0.f;
        for (int i = lane; i < 800; i += 32) a += sf[i] * w1[(long long)j * 800 + i];
        for (int o = 16; o; o >>= 1) a += __shfl_down_sync(0xffffffffu, a, o);
        if (lane == 0) s1[j] = fmaxf(a + b1[j], 0.f);
    }
    __syncthreads();
    if (tid < 128) {
        float a = b2[tid];
        for (int i = 0; i < 256; i++) a += s1[i] * w2[tid * 256 + i];
        s2[tid] = fmaxf(a, 0.f);
    }
    __syncthreads();
    if (tid < 2) {
        float a = b3[tid];
        for (int i = 0; i < 128; i++) a += s2[i] * w3[tid * 128 + i];
        out[b * 2 + tid] = a;
    }
}

// ---------------- launcher ----------------
extern "C" void kernel_launch(void* const* d_in, const int* in_sizes, int n_in,
                              void* d_out, int out_size) {
    const float* x     = (const float*)d_in[0];
    const int*   ei    = (const int*)  d_in[1];
    const int*   ids   = (const int*)  d_in[2];
    const float* etab  = (const float*)d_in[3];
    const float* ggcw  = (const float*)d_in[4];
    const float* wih   = (const float*)d_in[5];
    const float* whh   = (const float*)d_in[6];
    const float* bih   = (const float*)d_in[7];
    const float* bhh   = (const float*)d_in[8];
    const float* c0w   = (const float*)d_in[9];
    const float* c0b   = (const float*)d_in[10];
    const float* c1w   = (const float*)d_in[11];
    const float* c1b   = (const float*)d_in[12];
    const float* c2w   = (const float*)d_in[13];
    const float* c2b   = (const float*)d_in[14];
    const float* c3w   = (const float*)d_in[15];
    const float* c3b   = (const float*)d_in[16];
    const float* f1w   = (const float*)d_in[17];
    const float* f1b   = (const float*)d_in[18];
    const float* f2w   = (const float*)d_in[19];
    const float* f2b   = (const float*)d_in[20];
    const float* f3w   = (const float*)d_in[21];
    const float* f3b   = (const float*)d_in[22];
    float* out = (float*)d_out;

    float *h0, *h1, *gi, *gh, *feats;
    int *deg, *rs, *cur, *cs;
    __half *e16, *w1h, *w2h, *w3h, *hp16, *w0h;
    __half *h16, *a16, *wi16, *wh16, *wgd16, *wc16;
    cudaGetSymbolAddress((void**)&h0,   g_h0);
    cudaGetSymbolAddress((void**)&h1,   g_h1);
    cudaGetSymbolAddress((void**)&gi,   g_gi);
    cudaGetSymbolAddress((void**)&gh,   g_gh);
    cudaGetSymbolAddress((void**)&feats,g_feats);
    cudaGetSymbolAddress((void**)&deg,  g_deg);
    cudaGetSymbolAddress((void**)&rs,   g_rs);
    cudaGetSymbolAddress((void**)&cur,  g_cur);
    cudaGetSymbolAddress((void**)&cs,   g_csrc);
    cudaGetSymbolAddress((void**)&e16,  g_e16);
    cudaGetSymbolAddress((void**)&w1h,  g_w1h);
    cudaGetSymbolAddress((void**)&w2h,  g_w2h);
    cudaGetSymbolAddress((void**)&w3h,  g_w3h);
    cudaGetSymbolAddress((void**)&hp16, g_hp16);
    cudaGetSymbolAddress((void**)&w0h,  g_w0h);
    cudaGetSymbolAddress((void**)&h16,  g_h16);
    cudaGetSymbolAddress((void**)&a16,  g_a16);
    cudaGetSymbolAddress((void**)&wi16, g_wi16);
    cudaGetSymbolAddress((void**)&wh16, g_wh16);
    cudaGetSymbolAddress((void**)&wgd16,g_wgd16);
    cudaGetSymbolAddress((void**)&wc16, g_wc16);

    const int CONV3_SMEM = 36864 + 32256 + 448 + 448;   // 70016 B (2 CTAs/SM)
    const int CONV0_SMEM = 36864 + 59904 + 832 + 832;   // 98432 B
    const int GGC_SMEM   = 36864 + 59904;               // 96768 B
    cudaFuncSetAttribute(conv3h_k, cudaFuncAttributeMaxDynamicSharedMemorySize, CONV3_SMEM);
    cudaFuncSetAttribute(conv0h_k, cudaFuncAttributeMaxDynamicSharedMemorySize, CONV0_SMEM);
    cudaFuncSetAttribute(ggcN_k,   cudaFuncAttributeMaxDynamicSharedMemorySize, GGC_SMEM);
    cudaFuncSetAttribute(wcomb_k,  cudaFuncAttributeMaxDynamicSharedMemorySize, GGC_SMEM);

    // streams + events (created once; host resources, no device allocs)
    static cudaStream_t s2 = nullptr, s3 = nullptr;
    static cudaEvent_t ev1 = nullptr, ev2 = nullptr, evCSR = nullptr;
    static cudaEvent_t evG = nullptr, evB = nullptr;
    if (!s2) {
        cudaStreamCreateWithFlags(&s2, cudaStreamNonBlocking);
        cudaStreamCreateWithFlags(&s3, cudaStreamNonBlocking);
        cudaEventCreateWithFlags(&ev1,   cudaEventDisableTiming);
        cudaEventCreateWithFlags(&ev2,   cudaEventDisableTiming);
        cudaEventCreateWithFlags(&evCSR, cudaEventDisableTiming);
        cudaEventCreateWithFlags(&evG,   cudaEventDisableTiming);
        cudaEventCreateWithFlags(&evB,   cudaEventDisableTiming);
    }

    // ---- default stream: feats zero, then fork conv branch ----
    cudaMemsetAsync(feats, 0, BATCH * 800 * sizeof(float));
    cudaEventRecord(ev1, 0);
    cudaStreamWaitEvent(s2, ev1, 0);
    cudaStreamWaitEvent(s3, ev1, 0);

    // ---- side stream s2: conv1/2/3 branch (independent of GGC) ----
    k_embed16<<<BATCH * SEQ + 8, 192, 0, s2>>>(ids, etab, e16);
    k_w16<<<(200 * 768 * 3 + 255) / 256, 256, 0, s2>>>(c1w, w1h, 3);
    k_w16<<<(200 * 768 * 4 + 255) / 256, 256, 0, s2>>>(c2w, w2h, 4);
    k_w16<<<(200 * 768 * 5 + 255) / 256, 256, 0, s2>>>(c3w, w3h, 5);
    {
        Conv3Args ca;
        ca.wb[0] = w1h; ca.wb[1] = w2h; ca.wb[2] = w3h;
        ca.bias[0] = c1b; ca.bias[1] = c2b; ca.bias[2] = c3b;
        conv3h_k<<<dim3(6, 4, BATCH), 256, CONV3_SMEM, s2>>>(e16, ca, feats);
    }
    cudaEventRecord(ev2, s2);

    // ---- side stream s3: CSR build (needed only by first k_agg) ----
    cudaMemsetAsync(deg, 0, N_NODES * sizeof(int), s3);
    k_hist<<<(NEDGE + 255) / 256, 256, 0, s3>>>(ei, deg);
    k_scan<<<1, 1024, 0, s3>>>(deg, rs, cur, N_NODES);
    k_fill<<<(NEDGE + 255) / 256, 256, 0, s3>>>(ei, cur, cs);
    cudaEventRecord(evCSR, s3);

    // ---- default stream: GGC weight prep (overlaps CSR) ----
    cudaMemcpyAsync(h0, x, (size_t)N_NODES * HDIM * sizeof(float),
                    cudaMemcpyDeviceToDevice);
    k_x16<<<(N_NODES * KPAD + 255) / 256, 256>>>(x, h16);
    k_wgd16<<<(NLAYERS * 208 * KPAD + 255) / 256, 256>>>(ggcw, wgd16);
    k_wgru16<<<(640 * KPAD + 255) / 256, 256>>>(wih, wi16);
    k_wgru16<<<(640 * KPAD + 255) / 256, 256>>>(whh, wh16);
    k_w0h<<<(200 * 600 + 255) / 256, 256>>>(c0w, w0h);
    wcomb_k<<<dim3(1, 5, NLAYERS), 256, GGC_SMEM>>>(wi16, wgd16, wc16);
    cudaStreamWaitEvent(0, evCSR, 0);

    // ---- gated graph conv: 6 layers; gh on s3 overlaps k_agg+gi on main ----
    float* hc = h0;
    float* hn = h1;
    for (int l = 0; l < NLAYERS; l++) {
        cudaEventRecord(evG, 0);
        cudaStreamWaitEvent(s3, evG, 0);
        ggcN_k<<<dim3(3, NPER), 256, GGC_SMEM, s3>>>(h16, wh16, gh);
        cudaEventRecord(evB, s3);
        k_agg<<<(N_NODES + 7) / 8, 256>>>(hc, rs, cs, a16);
        ggcN_k<<<dim3(3, NPER), 256, GGC_SMEM>>>(a16,
                                                 wc16 + (long long)l * 640 * KPAD, gi);
        cudaStreamWaitEvent(0, evB, 0);
        k_gates<<<(N_NODES * HDIM + 255) / 256, 256>>>(
            gi, gh, bih, bhh, hc, hn, h16,
            (l == NLAYERS - 1) ? hp16 : (__half*)nullptr);
        float* t = hc; hc = hn; hn = t;
    }

    // ---- conv0 (fp16 HMMA, fused bias+ReLU+max; feats cols 0..199) ----
    conv0h_k<<<dim3(1, 2, BATCH), 256, CONV0_SMEM>>>(hp16, w0h, c0b, feats);

    // ---- join conv branch, then FC head ----
    cudaStreamWaitEvent(0, ev2, 0);
    k_fc<<<BATCH, 256>>>(feats, f1w, f1b, f2w, f2b, f3w, f3b, out);
}